// round 5
// baseline (speedup 1.0000x reference)
#include <cuda_runtime.h>
#include <math_constants.h>

#define BATCH   8
#define G       32
#define NCELLS  (G * G * G)          // 32768
#define NSEG    (2 * BATCH)          // 16 segments (set, batch)
#define MAXPTS  65536                // B*(N+M)
#define LO      (-5.12f)
#define CS      0.32f
#define INV_CS  3.125f
#define HI      (LO + G * CS)
#define BLOCK   256

__device__ unsigned g_count [NSEG * NCELLS];   // histogram -> scatter cursor
__device__ uint2    g_cell  [NSEG * NCELLS];   // (start, count)
__device__ float4   g_pts   [MAXPTS];          // sorted packed (-2x,-2y,-2z,|t|^2)

__device__ __forceinline__ int cell1(float v) {
    int i = (int)floorf((v - LO) * INV_CS);
    return min(max(i, 0), G - 1);
}

// ---------------------------------------------------------------- clear
__global__ void k_clear(float* out) {
    const int i = blockIdx.x * blockDim.x + threadIdx.x;   // NSEG*NCELLS/4 uint4
    ((uint4*)g_count)[i] = make_uint4(0, 0, 0, 0);
    if (i == 0) out[0] = 0.0f;
}

// ---------------------------------------------------------------- count
__global__ void k_count(const float* __restrict__ A, const float* __restrict__ Bp,
                        int N, int M) {
    const int tid = blockIdx.x * blockDim.x + threadIdx.x;
    const int BN = BATCH * N;
    if (tid >= BN + BATCH * M) return;
    int set, b, i;
    const float* src;
    if (tid < BN) { set = 0; b = tid / N; i = tid % N; src = A + (size_t)(b * N + i) * 3; }
    else { set = 1; const int r = tid - BN; b = r / M; i = r % M; src = Bp + (size_t)(b * M + i) * 3; }
    const int cid = (cell1(src[0]) * G + cell1(src[1])) * G + cell1(src[2]);
    atomicAdd(&g_count[(set * BATCH + b) * NCELLS + cid], 1u);
}

// ---------------------------------------------------------------- scan (1 block / segment)
__global__ __launch_bounds__(1024) void k_scan() {
    const int base = blockIdx.x * NCELLS;
    const int t = threadIdx.x;
    __shared__ unsigned sh[1024];

    const int c0 = t * (NCELLS / 1024);     // 32 cells per thread
    unsigned sum = 0;
    unsigned loc[NCELLS / 1024];
    #pragma unroll
    for (int k = 0; k < NCELLS / 1024; k++) { loc[k] = g_count[base + c0 + k]; sum += loc[k]; }
    sh[t] = sum;
    __syncthreads();
    for (int off = 1; off < 1024; off <<= 1) {
        unsigned v = (t >= off) ? sh[t - off] : 0u;
        __syncthreads();
        sh[t] += v;
        __syncthreads();
    }
    unsigned run = (t == 0) ? 0u : sh[t - 1];
    #pragma unroll
    for (int k = 0; k < NCELLS / 1024; k++) {
        const int c = base + c0 + k;
        g_cell[c] = make_uint2(run, loc[k]);
        g_count[c] = run;                    // becomes the scatter cursor
        run += loc[k];
    }
}

// ---------------------------------------------------------------- scatter
__global__ void k_scatter(const float* __restrict__ A, const float* __restrict__ Bp,
                          int N, int M) {
    const int tid = blockIdx.x * blockDim.x + threadIdx.x;
    const int BN = BATCH * N;
    if (tid >= BN + BATCH * M) return;
    int set, b, i, pbase;
    const float* src;
    if (tid < BN) { set = 0; b = tid / N; i = tid % N;
                    src = A + (size_t)(b * N + i) * 3; pbase = b * N; }
    else { set = 1; const int r = tid - BN; b = r / M; i = r % M;
           src = Bp + (size_t)(b * M + i) * 3; pbase = BN + b * M; }
    const float x = src[0], y = src[1], z = src[2];
    const int cid = (cell1(x) * G + cell1(y)) * G + cell1(z);
    const unsigned pos = atomicAdd(&g_count[(set * BATCH + b) * NCELLS + cid], 1u);
    g_pts[pbase + pos] = make_float4(-2.f * x, -2.f * y, -2.f * z,
                                     x * x + y * y + z * z);
}

// ---------------------------------------------------------------- query (warp-coherent)
// Each warp: 32 consecutive SORTED queries of one segment. All control flow and
// all g_cell / candidate loads are warp-uniform (broadcast); only the FMA uses
// per-lane query coords. Shell loop over the warp's union cell box.
__global__ __launch_bounds__(BLOCK) void k_query(int N, int M,
                                                 float inv1, float inv2,
                                                 float* __restrict__ out) {
    const int tid = blockIdx.x * blockDim.x + threadIdx.x;
    const int BN = BATCH * N;
    const int total = BN + BATCH * M;

    float contrib = 0.0f;
    if (tid < total) {
        int side, b, qoff, qbase, refbase;
        if (tid < BN) { side = 0; b = tid / N; qoff = tid % N;
                        qbase = b * N; refbase = BN + b * M; }
        else { side = 1; const int r = tid - BN; b = r / M; qoff = r % M;
               qbase = BN + b * M; refbase = b * N; }
        const int refseg = ((side ^ 1) * BATCH + b) * NCELLS;

        const float4 q4 = g_pts[qbase + qoff];
        const float qx = -0.5f * q4.x, qy = -0.5f * q4.y, qz = -0.5f * q4.z;
        const float qw = q4.w;
        const bool prune = (qx >= LO && qx < HI && qy >= LO && qy < HI &&
                            qz >= LO && qz < HI);
        const int cx = cell1(qx), cy = cell1(qy), cz = cell1(qz);

        // Warp-union cell box.
        const unsigned full = 0xffffffffu;
        const int bx0 = __reduce_min_sync(full, cx), bx1 = __reduce_max_sync(full, cx);
        const int by0 = __reduce_min_sync(full, cy), by1 = __reduce_max_sync(full, cy);
        const int bz0 = __reduce_min_sync(full, cz), bz1 = __reduce_max_sync(full, cz);

        float best = CUDART_INF_F;     // best partial = |t|^2 - 2 t.q

        for (int s = 0; s <= G; s++) {
            if (s >= 1) {
                const float r = (float)(s - 1) * CS;
                const bool done = prune && (r * r > qw + best);
                if (__all_sync(full, done)) break;
            }
            const int X0 = max(bx0 - s, 0), X1 = min(bx1 + s, G - 1);
            const int Y0 = max(by0 - s, 0), Y1 = min(by1 + s, G - 1);
            const int Z0 = max(bz0 - s, 0), Z1 = min(bz1 + s, G - 1);
            // previous expanded box (only meaningful for s >= 1)
            const int pX0 = max(bx0 - (s - 1), 0), pX1 = min(bx1 + (s - 1), G - 1);
            const int pY0 = max(by0 - (s - 1), 0), pY1 = min(by1 + (s - 1), G - 1);
            const int pZ0 = max(bz0 - (s - 1), 0), pZ1 = min(bz1 + (s - 1), G - 1);

            for (int xi = X0; xi <= X1; xi++) {
                const bool xnew = (s == 0) || (xi < pX0) || (xi > pX1);
                for (int yi = Y0; yi <= Y1; yi++) {
                    const bool fresh = xnew || (s == 0) || (yi < pY0) || (yi > pY1);
                    const int rowc = refseg + (xi * G + yi) * G;
                    int za = Z0, zb = Z1, zc = 1, zd = 0;   // ranges [za,zb] and [zc,zd]
                    if (!fresh) { za = Z0; zb = pZ0 - 1; zc = pZ1 + 1; zd = Z1; }
                    for (int zi = za; zi <= zb; zi++) {
                        const uint2 sc = g_cell[rowc + zi];
                        const float4* tp = &g_pts[refbase + sc.x];
                        for (unsigned j = 0; j < sc.y; j++) {
                            const float4 t4 = tp[j];
                            best = fminf(best, fmaf(t4.z, qz,
                                          fmaf(t4.y, qy,
                                          fmaf(t4.x, qx, t4.w))));
                        }
                    }
                    for (int zi = zc; zi <= zd; zi++) {
                        const uint2 sc = g_cell[rowc + zi];
                        const float4* tp = &g_pts[refbase + sc.x];
                        for (unsigned j = 0; j < sc.y; j++) {
                            const float4 t4 = tp[j];
                            best = fminf(best, fmaf(t4.z, qz,
                                          fmaf(t4.y, qy,
                                          fmaf(t4.x, qx, t4.w))));
                        }
                    }
                }
            }
            if (X0 == 0 && Y0 == 0 && Z0 == 0 &&
                X1 == G - 1 && Y1 == G - 1 && Z1 == G - 1) break;  // grid covered
        }
        contrib = fmaxf(qw + best, 0.0f) * (side ? inv2 : inv1);
    }

    // block reduction
    #pragma unroll
    for (int o = 16; o > 0; o >>= 1)
        contrib += __shfl_down_sync(0xffffffffu, contrib, o);
    __shared__ float wsum[BLOCK / 32];
    if ((threadIdx.x & 31) == 0) wsum[threadIdx.x >> 5] = contrib;
    __syncthreads();
    if (threadIdx.x < BLOCK / 32) {
        float v = wsum[threadIdx.x];
        #pragma unroll
        for (int o = BLOCK / 64; o > 0; o >>= 1)
            v += __shfl_down_sync(0xffu, v, o);
        if (threadIdx.x == 0) atomicAdd(out, v);
    }
}

// ---------------------------------------------------------------- launch
extern "C" void kernel_launch(void* const* d_in, const int* in_sizes, int n_in,
                              void* d_out, int out_size)
{
    const float* input  = (const float*)d_in[0];   // [B, N, 3]
    const float* target = (const float*)d_in[1];   // [B, M, 3]
    float* out = (float*)d_out;

    const int B = BATCH, D = 3;
    const int N = in_sizes[0] / (B * D);
    const int M = in_sizes[1] / (B * D);
    const int total = B * (N + M);

    k_clear<<<(NSEG * NCELLS / 4 + BLOCK - 1) / BLOCK, BLOCK>>>(out);
    k_count<<<(total + BLOCK - 1) / BLOCK, BLOCK>>>(input, target, N, M);
    k_scan<<<NSEG, 1024>>>();
    k_scatter<<<(total + BLOCK - 1) / BLOCK, BLOCK>>>(input, target, N, M);
    k_query<<<(total + BLOCK - 1) / BLOCK, BLOCK>>>(
        N, M, 1.0f / ((float)B * (float)N), 1.0f / ((float)B * (float)M), out);
}

// round 6
// speedup vs baseline: 3.3728x; 3.3728x over previous
#include <cuda_runtime.h>
#include <math_constants.h>

#define BATCH   8
#define G       16
#define NCELLS  (G * G * G)          // 4096
#define NSEG    (2 * BATCH)          // 16 segments (set, batch)
#define MAXPTS  65536                // B*(N+M)
#define LO      (-5.12f)
#define CS      0.64f
#define INV_CS  1.5625f
#define HI      (LO + G * CS)
#define BLOCK   256

__device__ unsigned g_count [NSEG * NCELLS];   // histogram -> scatter cursor
__device__ uint2    g_cell  [NSEG * NCELLS];   // (start, count), Morton-indexed
__device__ float4   g_pts   [MAXPTS];          // Morton-sorted packed (-2x,-2y,-2z,|t|^2)

__device__ __forceinline__ int cell1(float v) {
    int i = (int)floorf((v - LO) * INV_CS);
    return min(max(i, 0), G - 1);
}
// spread 4 bits to positions 0,3,6,9
__device__ __forceinline__ unsigned spread4(unsigned v) {
    return (v & 1u) | ((v & 2u) << 2) | ((v & 4u) << 4) | ((v & 8u) << 6);
}
__device__ __forceinline__ unsigned morton(int cx, int cy, int cz) {
    return (spread4((unsigned)cx) << 2) | (spread4((unsigned)cy) << 1)
         | spread4((unsigned)cz);
}

// ---------------------------------------------------------------- clear
__global__ void k_clear(float* out) {
    const int i = blockIdx.x * blockDim.x + threadIdx.x;   // NSEG*NCELLS/4 uint4
    ((uint4*)g_count)[i] = make_uint4(0, 0, 0, 0);
    if (i == 0) out[0] = 0.0f;
}

// ---------------------------------------------------------------- count
__global__ void k_count(const float* __restrict__ A, const float* __restrict__ Bp,
                        int N, int M) {
    const int tid = blockIdx.x * blockDim.x + threadIdx.x;
    const int BN = BATCH * N;
    if (tid >= BN + BATCH * M) return;
    int set, b, i;
    const float* src;
    if (tid < BN) { set = 0; b = tid / N; i = tid % N; src = A + (size_t)(b * N + i) * 3; }
    else { set = 1; const int r = tid - BN; b = r / M; i = r % M; src = Bp + (size_t)(b * M + i) * 3; }
    const unsigned cid = morton(cell1(src[0]), cell1(src[1]), cell1(src[2]));
    atomicAdd(&g_count[(set * BATCH + b) * NCELLS + cid], 1u);
}

// ---------------------------------------------------------------- scan (1 block / segment)
__global__ __launch_bounds__(1024) void k_scan() {
    const int base = blockIdx.x * NCELLS;
    const int t = threadIdx.x;
    __shared__ unsigned sh[1024];

    const int c0 = t * (NCELLS / 1024);     // 4 cells per thread
    unsigned loc[NCELLS / 1024];
    unsigned sum = 0;
    #pragma unroll
    for (int k = 0; k < NCELLS / 1024; k++) { loc[k] = g_count[base + c0 + k]; sum += loc[k]; }
    sh[t] = sum;
    __syncthreads();
    for (int off = 1; off < 1024; off <<= 1) {
        unsigned v = (t >= off) ? sh[t - off] : 0u;
        __syncthreads();
        sh[t] += v;
        __syncthreads();
    }
    unsigned run = (t == 0) ? 0u : sh[t - 1];
    #pragma unroll
    for (int k = 0; k < NCELLS / 1024; k++) {
        const int c = base + c0 + k;
        g_cell[c] = make_uint2(run, loc[k]);
        g_count[c] = run;                    // becomes the scatter cursor
        run += loc[k];
    }
}

// ---------------------------------------------------------------- scatter
__global__ void k_scatter(const float* __restrict__ A, const float* __restrict__ Bp,
                          int N, int M) {
    const int tid = blockIdx.x * blockDim.x + threadIdx.x;
    const int BN = BATCH * N;
    if (tid >= BN + BATCH * M) return;
    int set, b, i, pbase;
    const float* src;
    if (tid < BN) { set = 0; b = tid / N; i = tid % N;
                    src = A + (size_t)(b * N + i) * 3; pbase = b * N; }
    else { set = 1; const int r = tid - BN; b = r / M; i = r % M;
           src = Bp + (size_t)(b * M + i) * 3; pbase = BN + b * M; }
    const float x = src[0], y = src[1], z = src[2];
    const unsigned cid = morton(cell1(x), cell1(y), cell1(z));
    const unsigned pos = atomicAdd(&g_count[(set * BATCH + b) * NCELLS + cid], 1u);
    g_pts[pbase + pos] = make_float4(-2.f * x, -2.f * y, -2.f * z,
                                     x * x + y * y + z * z);
}

// ---------------------------------------------------------------- query (warp-coherent, Morton)
// Lanes = 32 consecutive MORTON-sorted queries (compact box). Cell descriptor
// loads, candidate loads and all control flow are warp-uniform; only the FMA
// uses per-lane query coords. Expanding Chebyshev shells over the union box,
// per-lane lower-bound prune + warp-vote break.
__global__ __launch_bounds__(BLOCK) void k_query(int N, int M,
                                                 float inv1, float inv2,
                                                 float* __restrict__ out) {
    const int tid = blockIdx.x * blockDim.x + threadIdx.x;
    const int BN = BATCH * N;

    int side, b, qoff, qbase, refbase;
    if (tid < BN) { side = 0; b = tid / N; qoff = tid % N;
                    qbase = b * N; refbase = BN + b * M; }
    else { side = 1; const int r = tid - BN; b = r / M; qoff = r % M;
           qbase = BN + b * M; refbase = b * N; }
    const int refseg = ((side ^ 1) * BATCH + b) * NCELLS;

    const float4 q4 = g_pts[qbase + qoff];
    const float qx = -0.5f * q4.x, qy = -0.5f * q4.y, qz = -0.5f * q4.z;
    const float qw = q4.w;
    const bool prune = (qx >= LO && qx < HI && qy >= LO && qy < HI &&
                        qz >= LO && qz < HI);
    const int cx = cell1(qx), cy = cell1(qy), cz = cell1(qz);

    const unsigned full = 0xffffffffu;
    const int bx0 = __reduce_min_sync(full, cx), bx1 = __reduce_max_sync(full, cx);
    const int by0 = __reduce_min_sync(full, cy), by1 = __reduce_max_sync(full, cy);
    const int bz0 = __reduce_min_sync(full, cz), bz1 = __reduce_max_sync(full, cz);

    float best = CUDART_INF_F;     // best partial = |t|^2 - 2 t.q

    for (int s = 0; s <= G; s++) {
        if (s >= 1) {
            const float r = (float)(s - 1) * CS;
            const bool done = prune && (r * r > qw + best);
            if (__all_sync(full, done)) break;
        }
        const int X0 = max(bx0 - s, 0), X1 = min(bx1 + s, G - 1);
        const int Y0 = max(by0 - s, 0), Y1 = min(by1 + s, G - 1);
        const int Z0 = max(bz0 - s, 0), Z1 = min(bz1 + s, G - 1);
        const int pX0 = max(bx0 - (s - 1), 0), pX1 = min(bx1 + (s - 1), G - 1);
        const int pY0 = max(by0 - (s - 1), 0), pY1 = min(by1 + (s - 1), G - 1);
        const int pZ0 = max(bz0 - (s - 1), 0), pZ1 = min(bz1 + (s - 1), G - 1);

        for (int xi = X0; xi <= X1; xi++) {
            const unsigned mx = spread4((unsigned)xi) << 2;
            const bool xnew = (s == 0) || (xi < pX0) || (xi > pX1);
            for (int yi = Y0; yi <= Y1; yi++) {
                const unsigned mxy = mx | (spread4((unsigned)yi) << 1);
                const bool fresh = xnew || (yi < pY0) || (yi > pY1);
                int za = Z0, zb = Z1, zc = 1, zd = 0;
                if (!fresh) { zb = pZ0 - 1; zc = pZ1 + 1; zd = Z1; }
                for (int zi = za; zi <= zb; zi++) {
                    const uint2 sc = g_cell[refseg + (mxy | spread4((unsigned)zi))];
                    const float4* tp = &g_pts[refbase + sc.x];
                    for (unsigned j = 0; j < sc.y; j++) {
                        const float4 t4 = tp[j];
                        best = fminf(best, fmaf(t4.z, qz,
                                      fmaf(t4.y, qy,
                                      fmaf(t4.x, qx, t4.w))));
                    }
                }
                for (int zi = zc; zi <= zd; zi++) {
                    const uint2 sc = g_cell[refseg + (mxy | spread4((unsigned)zi))];
                    const float4* tp = &g_pts[refbase + sc.x];
                    for (unsigned j = 0; j < sc.y; j++) {
                        const float4 t4 = tp[j];
                        best = fminf(best, fmaf(t4.z, qz,
                                      fmaf(t4.y, qy,
                                      fmaf(t4.x, qx, t4.w))));
                    }
                }
            }
        }
        if (X0 == 0 && Y0 == 0 && Z0 == 0 &&
            X1 == G - 1 && Y1 == G - 1 && Z1 == G - 1) break;  // grid covered
    }
    float contrib = fmaxf(qw + best, 0.0f) * (side ? inv2 : inv1);

    // block reduction
    #pragma unroll
    for (int o = 16; o > 0; o >>= 1)
        contrib += __shfl_down_sync(0xffffffffu, contrib, o);
    __shared__ float wsum[BLOCK / 32];
    if ((threadIdx.x & 31) == 0) wsum[threadIdx.x >> 5] = contrib;
    __syncthreads();
    if (threadIdx.x < BLOCK / 32) {
        float v = wsum[threadIdx.x];
        #pragma unroll
        for (int o = BLOCK / 64; o > 0; o >>= 1)
            v += __shfl_down_sync(0xffu, v, o);
        if (threadIdx.x == 0) atomicAdd(out, v);
    }
}

// ---------------------------------------------------------------- launch
extern "C" void kernel_launch(void* const* d_in, const int* in_sizes, int n_in,
                              void* d_out, int out_size)
{
    const float* input  = (const float*)d_in[0];   // [B, N, 3]
    const float* target = (const float*)d_in[1];   // [B, M, 3]
    float* out = (float*)d_out;

    const int B = BATCH, D = 3;
    const int N = in_sizes[0] / (B * D);
    const int M = in_sizes[1] / (B * D);
    const int total = B * (N + M);

    k_clear<<<(NSEG * NCELLS / 4 + BLOCK - 1) / BLOCK, BLOCK>>>(out);
    k_count<<<(total + BLOCK - 1) / BLOCK, BLOCK>>>(input, target, N, M);
    k_scan<<<NSEG, 1024>>>();
    k_scatter<<<(total + BLOCK - 1) / BLOCK, BLOCK>>>(input, target, N, M);
    k_query<<<(total + BLOCK - 1) / BLOCK, BLOCK>>>(
        N, M, 1.0f / ((float)B * (float)N), 1.0f / ((float)B * (float)M), out);
}

// round 8
// speedup vs baseline: 6.9342x; 2.0559x over previous
#include <cuda_runtime.h>
#include <math_constants.h>

#define BATCH   8
#define G       32
#define NCELLS  (G * G * G)          // 32768
#define NSEG    (2 * BATCH)          // 16 segments (set, batch)
#define MAXPTS  65536                // B*(N+M)
#define LO      (-5.12f)
#define CS      0.32f
#define INV_CS  3.125f
#define HI      (LO + G * CS)
#define BLOCK   256

__device__ unsigned g_count [NSEG * NCELLS];   // histogram -> scatter cursor
__device__ uint2    g_cell  [NSEG * NCELLS];   // (start, count), Morton-indexed
__device__ float4   g_pts   [MAXPTS];          // Morton-sorted packed (-2x,-2y,-2z,|t|^2)

__device__ __forceinline__ int cell1(float v) {
    int i = (int)floorf((v - LO) * INV_CS);
    return min(max(i, 0), G - 1);
}
// spread 5 bits to positions 0,3,6,9,12
__device__ __forceinline__ unsigned spread5(unsigned v) {
    return (v & 1u) | ((v & 2u) << 2) | ((v & 4u) << 4)
         | ((v & 8u) << 6) | ((v & 16u) << 8);
}
__device__ __forceinline__ unsigned morton(int cx, int cy, int cz) {
    return (spread5((unsigned)cx) << 2) | (spread5((unsigned)cy) << 1)
         | spread5((unsigned)cz);
}

// ---------------------------------------------------------------- clear
__global__ void k_clear(float* out) {
    const int i = blockIdx.x * blockDim.x + threadIdx.x;   // NSEG*NCELLS/4 uint4
    ((uint4*)g_count)[i] = make_uint4(0, 0, 0, 0);
    if (i == 0) out[0] = 0.0f;
}

// ---------------------------------------------------------------- count
__global__ void k_count(const float* __restrict__ A, const float* __restrict__ Bp,
                        int N, int M) {
    const int tid = blockIdx.x * blockDim.x + threadIdx.x;
    const int BN = BATCH * N;
    if (tid >= BN + BATCH * M) return;
    int set, b, i;
    const float* src;
    if (tid < BN) { set = 0; b = tid / N; i = tid % N; src = A + (size_t)(b * N + i) * 3; }
    else { set = 1; const int r = tid - BN; b = r / M; i = r % M; src = Bp + (size_t)(b * M + i) * 3; }
    const unsigned cid = morton(cell1(src[0]), cell1(src[1]), cell1(src[2]));
    atomicAdd(&g_count[(set * BATCH + b) * NCELLS + cid], 1u);
}

// ---------------------------------------------------------------- scan (1 block / segment)
__global__ __launch_bounds__(1024) void k_scan() {
    const int base = blockIdx.x * NCELLS;
    const int t = threadIdx.x;
    __shared__ unsigned sh[1024];

    const int c0 = t * (NCELLS / 1024);     // 32 cells per thread
    unsigned sum = 0;
    #pragma unroll 8
    for (int k = 0; k < NCELLS / 1024; k++) sum += g_count[base + c0 + k];
    sh[t] = sum;
    __syncthreads();
    for (int off = 1; off < 1024; off <<= 1) {
        unsigned v = (t >= off) ? sh[t - off] : 0u;
        __syncthreads();
        sh[t] += v;
        __syncthreads();
    }
    unsigned run = (t == 0) ? 0u : sh[t - 1];
    #pragma unroll 8
    for (int k = 0; k < NCELLS / 1024; k++) {
        const int c = base + c0 + k;
        const unsigned cnt = g_count[c];
        g_cell[c] = make_uint2(run, cnt);
        g_count[c] = run;                    // becomes the scatter cursor
        run += cnt;
    }
}

// ---------------------------------------------------------------- scatter
__global__ void k_scatter(const float* __restrict__ A, const float* __restrict__ Bp,
                          int N, int M) {
    const int tid = blockIdx.x * blockDim.x + threadIdx.x;
    const int BN = BATCH * N;
    if (tid >= BN + BATCH * M) return;
    int set, b, i, pbase;
    const float* src;
    if (tid < BN) { set = 0; b = tid / N; i = tid % N;
                    src = A + (size_t)(b * N + i) * 3; pbase = b * N; }
    else { set = 1; const int r = tid - BN; b = r / M; i = r % M;
           src = Bp + (size_t)(b * M + i) * 3; pbase = BN + b * M; }
    const float x = src[0], y = src[1], z = src[2];
    const unsigned cid = morton(cell1(x), cell1(y), cell1(z));
    const unsigned pos = atomicAdd(&g_count[(set * BATCH + b) * NCELLS + cid], 1u);
    g_pts[pbase + pos] = make_float4(-2.f * x, -2.f * y, -2.f * z,
                                     x * x + y * y + z * z);
}

// ILP-2 candidate scan over one cell (uniform addresses across the warp).
__device__ __forceinline__ void scan_cell(uint2 sc, const float4* __restrict__ base,
                                          float qx, float qy, float qz,
                                          float& b0, float& b1) {
    const float4* tp = base + sc.x;
    const unsigned n = sc.y;
    unsigned j = 0;
    for (; j + 2 <= n; j += 2) {
        const float4 a = tp[j];
        const float4 c = tp[j + 1];
        b0 = fminf(b0, fmaf(a.z, qz, fmaf(a.y, qy, fmaf(a.x, qx, a.w))));
        b1 = fminf(b1, fmaf(c.z, qz, fmaf(c.y, qy, fmaf(c.x, qx, c.w))));
    }
    if (j < n) {
        const float4 a = tp[j];
        b0 = fminf(b0, fmaf(a.z, qz, fmaf(a.y, qy, fmaf(a.x, qx, a.w))));
    }
}

// ---------------------------------------------------------------- query
// Warp-coherent, bounded: rings s=0..2 over the warp-union box (warp-uniform
// control flow + broadcast loads), exactness votes at (s*CS)^2; any lane not
// proven done falls back to a cooperative whole-warp scan of the full segment
// (coalesced, warp-reduced). Degenerate spread boxes skip rings entirely.
__global__ __launch_bounds__(BLOCK) void k_query(int N, int M,
                                                 float inv1, float inv2,
                                                 float* __restrict__ out) {
    const int tid = blockIdx.x * blockDim.x + threadIdx.x;
    const int BN = BATCH * N;
    const int lane = threadIdx.x & 31;
    const unsigned full = 0xffffffffu;

    int side, b, qraw, qbase, refbase, refM;
    if (tid < BN) { side = 0; b = tid / N; qraw = tid % N;
                    qbase = b * N; refbase = BN + b * M; refM = M; }
    else { side = 1; const int r = tid - BN; b = r / M; qraw = r % M;
           qbase = BN + b * M; refbase = b * N; refM = N; }
    const int refseg = ((side ^ 1) * BATCH + b) * NCELLS;

    // Permute warps within the segment (odd multiplier -> bijection) so heavy
    // (center) and light (tail) warps mix across blocks; lanes stay consecutive.
    const int Wq = (side ? M : N) >> 5;          // warps per segment (pow2: 128)
    const int qoff = ((((qraw >> 5) * 37) & (Wq - 1)) << 5) | lane;

    const float4 q4 = g_pts[qbase + qoff];
    const float qx = -0.5f * q4.x, qy = -0.5f * q4.y, qz = -0.5f * q4.z;
    const float qw = q4.w;
    const bool inbox = (qx >= LO && qx < HI && qy >= LO && qy < HI &&
                        qz >= LO && qz < HI);
    const int cx = cell1(qx), cy = cell1(qy), cz = cell1(qz);

    const int bx0 = __reduce_min_sync(full, cx), bx1 = __reduce_max_sync(full, cx);
    const int by0 = __reduce_min_sync(full, cy), by1 = __reduce_max_sync(full, cy);
    const int bz0 = __reduce_min_sync(full, cz), bz1 = __reduce_max_sync(full, cz);

    float b0 = CUDART_INF_F, b1 = CUDART_INF_F;   // partial = |t|^2 - 2 t.q
    bool done = false;

    const int ext = max(max(bx1 - bx0, by1 - by0), bz1 - bz0);
    const bool dorings = (ext <= 5);

    if (dorings) {
        const float4* segp = &g_pts[refbase];
        for (int s = 0; s <= 2; s++) {
            const int X0 = max(bx0 - s, 0), X1 = min(bx1 + s, G - 1);
            const int Y0 = max(by0 - s, 0), Y1 = min(by1 + s, G - 1);
            const int Z0 = max(bz0 - s, 0), Z1 = min(bz1 + s, G - 1);
            const int pX0 = max(bx0 - s + 1, 0), pX1 = min(bx1 + s - 1, G - 1);
            const int pY0 = max(by0 - s + 1, 0), pY1 = min(by1 + s - 1, G - 1);
            const int pZ0 = max(bz0 - s + 1, 0), pZ1 = min(bz1 + s - 1, G - 1);

            for (int xi = X0; xi <= X1; xi++) {
                const unsigned mx = spread5((unsigned)xi) << 2;
                const bool xnew = (s == 0) || (xi < pX0) || (xi > pX1);
                for (int yi = Y0; yi <= Y1; yi++) {
                    const unsigned mxy = mx | (spread5((unsigned)yi) << 1);
                    const bool fresh = xnew || (yi < pY0) || (yi > pY1);
                    int za = Z0, zb = Z1, zc = 1, zd = 0;
                    if (!fresh) { zb = pZ0 - 1; zc = pZ1 + 1; zd = Z1; }
                    for (int zi = za; zi <= zb; zi++)
                        scan_cell(g_cell[refseg + (mxy | spread5((unsigned)zi))],
                                  segp, qx, qy, qz, b0, b1);
                    for (int zi = zc; zi <= zd; zi++)
                        scan_cell(g_cell[refseg + (mxy | spread5((unsigned)zi))],
                                  segp, qx, qy, qz, b0, b1);
                }
            }
            if (s >= 1) {
                const float r = (float)s * CS;
                const bool ok = inbox && (fminf(b0, b1) <= r * r - qw);
                if (__all_sync(full, ok)) { done = true; break; }
            }
        }
        if (!done) {
            const float r = 2.0f * CS;
            done = inbox && (fminf(b0, b1) <= r * r - qw);
        }
    }

    float best = fminf(b0, b1);

    // Cooperative fallback: whole warp serves each not-done lane.
    unsigned need = __ballot_sync(full, !done);
    while (need) {
        const int q = __ffs(need) - 1;
        need &= need - 1;
        const float fx = __shfl_sync(full, qx, q);
        const float fy = __shfl_sync(full, qy, q);
        const float fz = __shfl_sync(full, qz, q);
        float m0 = CUDART_INF_F, m1 = CUDART_INF_F;
        int j = lane;
        for (; j + 32 < refM; j += 64) {
            const float4 a = g_pts[refbase + j];
            const float4 c = g_pts[refbase + j + 32];
            m0 = fminf(m0, fmaf(a.z, fz, fmaf(a.y, fy, fmaf(a.x, fx, a.w))));
            m1 = fminf(m1, fmaf(c.z, fz, fmaf(c.y, fy, fmaf(c.x, fx, c.w))));
        }
        if (j < refM) {
            const float4 a = g_pts[refbase + j];
            m0 = fminf(m0, fmaf(a.z, fz, fmaf(a.y, fy, fmaf(a.x, fx, a.w))));
        }
        float m = fminf(m0, m1);
        #pragma unroll
        for (int o = 16; o > 0; o >>= 1)
            m = fminf(m, __shfl_xor_sync(full, m, o));
        if (lane == q) best = fminf(best, m);
    }

    float contrib = fmaxf(qw + best, 0.0f) * (side ? inv2 : inv1);

    // block reduction
    #pragma unroll
    for (int o = 16; o > 0; o >>= 1)
        contrib += __shfl_down_sync(full, contrib, o);
    __shared__ float wsum[BLOCK / 32];
    if (lane == 0) wsum[threadIdx.x >> 5] = contrib;
    __syncthreads();
    if (threadIdx.x < BLOCK / 32) {
        float v = wsum[threadIdx.x];
        #pragma unroll
        for (int o = BLOCK / 64; o > 0; o >>= 1)
            v += __shfl_down_sync(0xffu, v, o);
        if (threadIdx.x == 0) atomicAdd(out, v);
    }
}

// ---------------------------------------------------------------- launch
extern "C" void kernel_launch(void* const* d_in, const int* in_sizes, int n_in,
                              void* d_out, int out_size)
{
    const float* input  = (const float*)d_in[0];   // [B, N, 3]
    const float* target = (const float*)d_in[1];   // [B, M, 3]
    float* out = (float*)d_out;

    const int B = BATCH, D = 3;
    const int N = in_sizes[0] / (B * D);
    const int M = in_sizes[1] / (B * D);
    const int total = B * (N + M);

    k_clear<<<(NSEG * NCELLS / 4 + BLOCK - 1) / BLOCK, BLOCK>>>(out);
    k_count<<<(total + BLOCK - 1) / BLOCK, BLOCK>>>(input, target, N, M);
    k_scan<<<NSEG, 1024>>>();
    k_scatter<<<(total + BLOCK - 1) / BLOCK, BLOCK>>>(input, target, N, M);
    k_query<<<(total + BLOCK - 1) / BLOCK, BLOCK>>>(
        N, M, 1.0f / ((float)B * (float)N), 1.0f / ((float)B * (float)M), out);
}

// round 10
// speedup vs baseline: 30.7851x; 4.4396x over previous
#include <cuda_runtime.h>
#include <math_constants.h>

#define BATCH 8
#define RPB   128          // rows per block
#define SC    128          // stripe cols
#define BLOCK 256
#define MAXG  32           // max row-groups (N/128)
#define MAXM  4096
#define MAXBM (BATCH * MAXM)

typedef unsigned long long ull;

__device__ unsigned g_colpart[MAXG * MAXBM];   // encoded col-min partials, [g][b][col]
__device__ float    g_rowsum [MAXG * BATCH];   // per-block scaled row-min sums

__device__ __forceinline__ ull ffma2(ull a, ull b, ull c) {
    ull d;
    asm("fma.rn.f32x2 %0, %1, %2, %3;" : "=l"(d) : "l"(a), "l"(b), "l"(c));
    return d;
}
__device__ __forceinline__ ull add2(ull a, ull b) {
    ull d;
    asm("add.rn.f32x2 %0, %1, %2;" : "=l"(d) : "l"(a), "l"(b));
    return d;
}
__device__ __forceinline__ void unpack2(ull s, float& lo, float& hi) {
    asm("mov.b64 {%0, %1}, %2;" : "=f"(lo), "=f"(hi) : "l"(s));
}
// Order-preserving float <-> uint (monotone over all floats incl. +/-inf).
__device__ __forceinline__ unsigned encf(float f) {
    unsigned b = __float_as_uint(f);
    return (b & 0x80000000u) ? ~b : (b | 0x80000000u);
}
__device__ __forceinline__ float decf(unsigned u) {
    unsigned b = (u & 0x80000000u) ? (u & 0x7FFFFFFFu) : ~u;
    return __uint_as_float(b);
}

// Fused both-pass kernel. Block (g, b): rows = input[b, g*128 .. +127], cols =
// all M targets, stripes of 128 cols staged in smem (packed col-pairs).
// Per pair (computed ONCE): s = |t|^2 - 2 t.p  (3 FFMA2 over 2 cols),
// d = s + |p|^2 (1 ADD2). Row-min accumulates s (add |p|^2 after the min);
// col-min accumulates d. Col partials -> smem atomicMin (spread addresses),
// flushed to g_colpart (each slot written exactly once -> no init pass).
__global__ __launch_bounds__(BLOCK) void chamfer_main(
    const float* __restrict__ input,   // [B, N, 3]
    const float* __restrict__ target,  // [B, M, 3]
    int N, int M, float inv1, float* __restrict__ out)
{
    __shared__ __align__(16) float Pa[RPB * 4];   // per row: px,px,py,py
    __shared__ __align__(16) float Pb[RPB * 4];   // per row: pz,pz,p2,p2
    __shared__ __align__(16) float Tx[SC], Ty[SC], Tz[SC], Tw[SC];
    __shared__ unsigned sCol[MAXM];
    __shared__ unsigned sRow[RPB];
    __shared__ float    wred[BLOCK / 32];

    const int g = blockIdx.x, b = blockIdx.y;
    const int tid = threadIdx.x;
    const int w = tid >> 5, l = tid & 31;

    if (g == 0 && b == 0 && tid == 0) out[0] = 0.0f;   // finalize runs after us

    for (int i = tid; i < M; i += BLOCK) sCol[i] = 0xFF800000u;   // enc(+inf)
    if (tid < RPB) {
        sRow[tid] = 0xFF800000u;
        const float* p = input + ((size_t)b * N + (size_t)g * RPB + tid) * 3;
        const float px = p[0], py = p[1], pz = p[2];
        const float p2 = px * px + py * py + pz * pz;
        ((float4*)Pa)[tid] = make_float4(px, px, py, py);
        ((float4*)Pb)[tid] = make_float4(pz, pz, p2, p2);
    }

    const float* tb = target + (size_t)b * M * 3;
    float tx = 0.f, ty = 0.f, tz = 0.f;
    if (tid < SC) { const float* q = tb + (size_t)tid * 3; tx = q[0]; ty = q[1]; tz = q[2]; }

    float rm[16];
    #pragma unroll
    for (int r = 0; r < 16; r++) rm[r] = CUDART_INF_F;

    const int nstripes = M / SC;
    const int f = l * 4;                   // lane's 4 private cols in the stripe

    for (int s = 0; s < nstripes; s++) {
        __syncthreads();                   // prior compute done; T writable
        if (tid < SC) {
            Tx[tid] = -2.f * tx; Ty[tid] = -2.f * ty; Tz[tid] = -2.f * tz;
            Tw[tid] = tx * tx + ty * ty + tz * tz;
        }
        __syncthreads();                   // T ready
        if (s + 1 < nstripes && tid < SC) {            // prefetch next stripe
            const float* q = tb + (size_t)((s + 1) * SC + tid) * 3;
            tx = q[0]; ty = q[1]; tz = q[2];
        }

        const ulonglong2 X  = *(const ulonglong2*)&Tx[f];
        const ulonglong2 Y  = *(const ulonglong2*)&Ty[f];
        const ulonglong2 Z  = *(const ulonglong2*)&Tz[f];
        const ulonglong2 W2 = *(const ulonglong2*)&Tw[f];

        float cm0 = CUDART_INF_F, cm1 = CUDART_INF_F;
        float cm2 = CUDART_INF_F, cm3 = CUDART_INF_F;

        #pragma unroll
        for (int r = 0; r < 16; r++) {
            const int row = w * 16 + r;
            const ulonglong2 A = ((const ulonglong2*)Pa)[row];  // (px,px),(py,py)
            const ulonglong2 C = ((const ulonglong2*)Pb)[row];  // (pz,pz),(p2,p2)
            ull s0 = ffma2(X.x, A.x, W2.x);
            s0     = ffma2(Y.x, A.y, s0);
            s0     = ffma2(Z.x, C.x, s0);
            ull s1 = ffma2(X.y, A.x, W2.y);
            s1     = ffma2(Y.y, A.y, s1);
            s1     = ffma2(Z.y, C.x, s1);
            const ull d0 = add2(s0, C.y);
            const ull d1 = add2(s1, C.y);
            float a0, a1, b0, b1, e0, e1, f0, f1;
            unpack2(s0, a0, a1);
            unpack2(s1, b0, b1);
            unpack2(d0, e0, e1);
            unpack2(d1, f0, f1);
            rm[r] = fminf(rm[r], fminf(fminf(a0, a1), fminf(b0, b1)));
            cm0 = fminf(cm0, e0); cm1 = fminf(cm1, e1);
            cm2 = fminf(cm2, f0); cm3 = fminf(cm3, f1);
        }

        const int cb = s * SC + f;         // spread addresses within the warp
        atomicMin(&sCol[cb + 0], encf(cm0));
        atomicMin(&sCol[cb + 1], encf(cm1));
        atomicMin(&sCol[cb + 2], encf(cm2));
        atomicMin(&sCol[cb + 3], encf(cm3));
    }

    #pragma unroll
    for (int r = 0; r < 16; r++)
        atomicMin(&sRow[w * 16 + r], encf(rm[r]));
    __syncthreads();

    // flush col partials (each slot written exactly once per launch)
    unsigned* cp = &g_colpart[(size_t)g * MAXBM + (size_t)b * M];
    for (int i = tid; i < M; i += BLOCK) cp[i] = sCol[i];

    // row side is complete: clamp, scale, block-sum
    float v = 0.f;
    if (tid < RPB) {
        const float p2 = Pb[tid * 4 + 2];
        v = fmaxf(decf(sRow[tid]) + p2, 0.f) * inv1;
    }
    #pragma unroll
    for (int o = 16; o > 0; o >>= 1) v += __shfl_down_sync(0xffffffffu, v, o);
    if (l == 0) wred[w] = v;
    __syncthreads();
    if (tid < BLOCK / 32) {
        float t = wred[tid];
        #pragma unroll
        for (int o = BLOCK / 64; o > 0; o >>= 1) t += __shfl_down_sync(0xffu, t, o);
        if (tid == 0) g_rowsum[b * gridDim.x + g] = t;
    }
}

// Finalize: per (b, col) min over the G row-block partials (encoded -> min
// commutes), clamp, mean; block 0 also folds in the pre-scaled row sums.
__global__ __launch_bounds__(BLOCK) void chamfer_final(
    float* __restrict__ out, int G, int M, int nrowsum, float inv2)
{
    const int e = blockIdx.x * BLOCK + threadIdx.x;    // 0 .. B*M-1
    unsigned mn = 0xFF800000u;
    for (int g = 0; g < G; g++)
        mn = min(mn, g_colpart[(size_t)g * MAXBM + e]);
    float v = fmaxf(decf(mn), 0.f) * inv2;
    if (blockIdx.x == 0 && threadIdx.x < nrowsum) v += g_rowsum[threadIdx.x];

    #pragma unroll
    for (int o = 16; o > 0; o >>= 1) v += __shfl_down_sync(0xffffffffu, v, o);
    __shared__ float wred[BLOCK / 32];
    if ((threadIdx.x & 31) == 0) wred[threadIdx.x >> 5] = v;
    __syncthreads();
    if (threadIdx.x < BLOCK / 32) {
        float t = wred[threadIdx.x];
        #pragma unroll
        for (int o = BLOCK / 64; o > 0; o >>= 1) t += __shfl_down_sync(0xffu, t, o);
        if (threadIdx.x == 0) atomicAdd(out, t);
    }
}

extern "C" void kernel_launch(void* const* d_in, const int* in_sizes, int n_in,
                              void* d_out, int out_size)
{
    const float* input  = (const float*)d_in[0];   // [B, N, 3]
    const float* target = (const float*)d_in[1];   // [B, M, 3]
    float* out = (float*)d_out;

    const int B = BATCH, D = 3;
    const int N = in_sizes[0] / (B * D);
    const int M = in_sizes[1] / (B * D);
    const int G = N / RPB;                          // 32

    dim3 grid(G, B);
    chamfer_main<<<grid, BLOCK>>>(input, target, N, M,
                                  1.0f / ((float)B * (float)N), out);
    chamfer_final<<<(B * M) / BLOCK, BLOCK>>>(out, G, M, G * B,
                                              1.0f / ((float)B * (float)M));
}

// round 11
// speedup vs baseline: 33.4126x; 1.0853x over previous
#include <cuda_runtime.h>
#include <math_constants.h>

#define BATCH 8
#define RPB   128          // rows per block
#define SC    128          // stripe cols
#define BLOCK 256
#define MAXG  32           // row-groups (N/128)
#define MAXM  4096
#define MAXBM (BATCH * MAXM)

typedef unsigned long long ull;

__device__ float g_colpart[MAXG * MAXBM];   // col-min partials, [g][b][col]
__device__ float g_rowsum [MAXG * BATCH];   // per-block scaled row-min sums

__device__ __forceinline__ ull ffma2(ull a, ull b, ull c) {
    ull d;
    asm("fma.rn.f32x2 %0, %1, %2, %3;" : "=l"(d) : "l"(a), "l"(b), "l"(c));
    return d;
}
__device__ __forceinline__ ull add2(ull a, ull b) {
    ull d;
    asm("add.rn.f32x2 %0, %1, %2;" : "=l"(d) : "l"(a), "l"(b));
    return d;
}
__device__ __forceinline__ void unpack2(ull s, float& lo, float& hi) {
    asm("mov.b64 {%0, %1}, %2;" : "=f"(lo), "=f"(hi) : "l"(s));
}

// Fused both-pass kernel, no atomics. Block (g, b): rows g*128..+127, all M
// cols in 128-col stripes. Warp w owns rows w*16..+15 (exclusive), lane owns
// cols f..f+3 of each stripe (exclusive). d computed ONCE per pair feeds both
// row-min (registers + end shuffle) and col-min (STS.128 per stripe, combined
// across warps by the idle half-block one stripe behind, then coalesced STG).
__global__ __launch_bounds__(BLOCK) void chamfer_main(
    const float* __restrict__ input,   // [B, N, 3]
    const float* __restrict__ target,  // [B, M, 3]
    int N, int M, float inv1, float* __restrict__ out)
{
    __shared__ __align__(16) float Pa[RPB * 4];   // per row: px,px,py,py
    __shared__ __align__(16) float Pb[RPB * 4];   // per row: pz,pz,p2,p2
    __shared__ __align__(16) float Tx[SC], Ty[SC], Tz[SC], Tw[SC];
    __shared__ __align__(16) float scm[2][8 * SC];  // [buf][warp][col]
    __shared__ float wred[BLOCK / 32];

    const int g = blockIdx.x, b = blockIdx.y;
    const int tid = threadIdx.x;
    const int w = tid >> 5, l = tid & 31;
    const int f = l * 4;

    if (g == 0 && b == 0 && tid == 0) out[0] = 0.0f;   // finalize runs after us

    if (tid < RPB) {
        const float* p = input + ((size_t)b * N + (size_t)g * RPB + tid) * 3;
        const float px = p[0], py = p[1], pz = p[2];
        const float p2 = px * px + py * py + pz * pz;
        ((float4*)Pa)[tid] = make_float4(px, px, py, py);
        ((float4*)Pb)[tid] = make_float4(pz, pz, p2, p2);
    }

    const float* tb = target + (size_t)b * M * 3;
    float tx = 0.f, ty = 0.f, tz = 0.f;
    if (tid < SC) { const float* q = tb + (size_t)tid * 3; tx = q[0]; ty = q[1]; tz = q[2]; }

    float rm[16];
    #pragma unroll
    for (int r = 0; r < 16; r++) rm[r] = CUDART_INF_F;

    float* cpb = &g_colpart[(size_t)g * MAXBM + (size_t)b * M];
    const int nstripes = M / SC;

    for (int s = 0; s < nstripes; s++) {
        __syncthreads();                   // A: prior compute done (scm ready)
        if (tid < SC) {                    // stage stripe s
            Tx[tid] = -2.f * tx; Ty[tid] = -2.f * ty; Tz[tid] = -2.f * tz;
            Tw[tid] = tx * tx + ty * ty + tz * tz;
        } else if (s > 0) {                // combine stripe s-1 cols (8 warps)
            const int c = tid - SC;
            const float* sm = scm[(s - 1) & 1];
            float m = sm[c];
            #pragma unroll
            for (int ww = 1; ww < 8; ww++) m = fminf(m, sm[ww * SC + c]);
            cpb[(s - 1) * SC + c] = m;     // coalesced, written exactly once
        }
        __syncthreads();                   // B: T ready
        if (s + 1 < nstripes && tid < SC) {            // prefetch next stripe
            const float* q = tb + (size_t)((s + 1) * SC + tid) * 3;
            tx = q[0]; ty = q[1]; tz = q[2];
        }

        const ulonglong2 X  = *(const ulonglong2*)&Tx[f];
        const ulonglong2 Y  = *(const ulonglong2*)&Ty[f];
        const ulonglong2 Z  = *(const ulonglong2*)&Tz[f];
        const ulonglong2 W2 = *(const ulonglong2*)&Tw[f];

        float cm0 = CUDART_INF_F, cm1 = CUDART_INF_F;
        float cm2 = CUDART_INF_F, cm3 = CUDART_INF_F;

        #pragma unroll
        for (int r = 0; r < 16; r++) {
            const int row = w * 16 + r;
            const ulonglong2 A = ((const ulonglong2*)Pa)[row];  // (px,px),(py,py)
            const ulonglong2 C = ((const ulonglong2*)Pb)[row];  // (pz,pz),(p2,p2)
            ull d0 = ffma2(X.x, A.x, add2(W2.x, C.y));
            d0     = ffma2(Y.x, A.y, d0);
            d0     = ffma2(Z.x, C.x, d0);
            ull d1 = ffma2(X.y, A.x, add2(W2.y, C.y));
            d1     = ffma2(Y.y, A.y, d1);
            d1     = ffma2(Z.y, C.x, d1);
            float e0, e1, f0, f1;
            unpack2(d0, e0, e1);
            unpack2(d1, f0, f1);
            rm[r] = fminf(rm[r], fminf(fminf(e0, e1), fminf(f0, f1)));
            cm0 = fminf(cm0, e0); cm1 = fminf(cm1, e1);
            cm2 = fminf(cm2, f0); cm3 = fminf(cm3, f1);
        }
        ((float4*)&scm[s & 1][w * SC])[l] = make_float4(cm0, cm1, cm2, cm3);
    }
    __syncthreads();                       // last stripe's scm visible
    if (tid >= SC) {                       // combine last stripe
        const int c = tid - SC;
        const float* sm = scm[(nstripes - 1) & 1];
        float m = sm[c];
        #pragma unroll
        for (int ww = 1; ww < 8; ww++) m = fminf(m, sm[ww * SC + c]);
        cpb[(nstripes - 1) * SC + c] = m;
    }

    // Row side: warp-exclusive rows; cross-lane min via shuffle, clamp, sum.
    float acc = 0.f;
    #pragma unroll
    for (int r = 0; r < 16; r++) {
        float v = rm[r];
        #pragma unroll
        for (int o = 16; o > 0; o >>= 1)
            v = fminf(v, __shfl_xor_sync(0xffffffffu, v, o));
        acc += fmaxf(v, 0.f);
    }
    if (l == 0) wred[w] = acc * inv1;
    __syncthreads();
    if (tid == 0) {
        float t = 0.f;
        #pragma unroll
        for (int ww = 0; ww < 8; ww++) t += wred[ww];
        g_rowsum[b * gridDim.x + g] = t;
    }
}

// Finalize: per (b, col) min over G row-block partials, clamp, mean; block 0
// folds in the pre-scaled row sums. 256 blocks x 128 threads, 32-deep MLP.
__global__ __launch_bounds__(128) void chamfer_final(
    float* __restrict__ out, int M, int nrowsum, float inv2)
{
    const int e = blockIdx.x * 128 + threadIdx.x;    // 0 .. B*M-1
    float mn = CUDART_INF_F;
    #pragma unroll
    for (int g = 0; g < MAXG; g++)
        mn = fminf(mn, g_colpart[(size_t)g * MAXBM + e]);
    float v = fmaxf(mn, 0.f) * inv2;
    if (blockIdx.x == 0) {
        v += g_rowsum[threadIdx.x];
        if (threadIdx.x + 128 < nrowsum) v += g_rowsum[threadIdx.x + 128];
    }

    #pragma unroll
    for (int o = 16; o > 0; o >>= 1) v += __shfl_down_sync(0xffffffffu, v, o);
    __shared__ float wred[4];
    if ((threadIdx.x & 31) == 0) wred[threadIdx.x >> 5] = v;
    __syncthreads();
    if (threadIdx.x < 4) {
        float t = wred[threadIdx.x];
        #pragma unroll
        for (int o = 2; o > 0; o >>= 1) t += __shfl_down_sync(0xfu, t, o);
        if (threadIdx.x == 0) atomicAdd(out, t);
    }
}

extern "C" void kernel_launch(void* const* d_in, const int* in_sizes, int n_in,
                              void* d_out, int out_size)
{
    const float* input  = (const float*)d_in[0];   // [B, N, 3]
    const float* target = (const float*)d_in[1];   // [B, M, 3]
    float* out = (float*)d_out;

    const int B = BATCH, D = 3;
    const int N = in_sizes[0] / (B * D);
    const int M = in_sizes[1] / (B * D);
    const int G = N / RPB;                          // 32

    dim3 grid(G, B);
    chamfer_main<<<grid, BLOCK>>>(input, target, N, M,
                                  1.0f / ((float)B * (float)N), out);
    chamfer_final<<<(B * M) / 128, 128>>>(out, M, G * B,
                                          1.0f / ((float)B * (float)M));
}